// round 1
// baseline (speedup 1.0000x reference)
#include <cuda_runtime.h>
#include <cuda_bf16.h>

// Problem constants (fixed shapes from setup_inputs)
#define BB 8
#define CC 8
#define HH 512
#define WW 1024
#define HWSZ (HH * WW)

#define TILE 32
#define BX 32
#define BY 8
#define RPT 4              // rows per thread (TILE / BY)
#define NQ 26              // quantities per batch: 8 sump, 8 inter, 8 cnt, ce, wce
#define NWARPS ((BX * BY) / 32)

// Global accumulators (scratch; no allocation allowed)
__device__ double g_acc[BB][NQ];

__global__ void zero_kernel() {
    int i = threadIdx.x;
    if (i < BB * NQ) ((double*)g_acc)[i] = 0.0;
}

__global__ __launch_bounds__(BX * BY) void loss_main_kernel(
    const float* __restrict__ pred, const int* __restrict__ target)
{
    __shared__ int s_t[TILE + 4][TILE + 4];
    __shared__ float s_red[NQ][NWARPS];

    const int b   = blockIdx.z;
    const int gx0 = blockIdx.x * TILE;
    const int gy0 = blockIdx.y * TILE;
    const int tx  = threadIdx.x;
    const int ty  = threadIdx.y;
    const int tid = ty * BX + tx;

    // ---- stage target halo tile (36x36); OOB = -1 ----
    // -1 is ignored by signed max (values >= 0) and by unsigned min (0xFFFFFFFF).
    const int* tgt_b = target + b * HWSZ;
    for (int i = tid; i < (TILE + 4) * (TILE + 4); i += BX * BY) {
        int ly = i / (TILE + 4), lx = i % (TILE + 4);
        int gy = gy0 + ly - 2, gx = gx0 + lx - 2;
        int v = -1;
        if (gy >= 0 && gy < HH && gx >= 0 && gx < WW) v = __ldg(tgt_b + gy * WW + gx);
        s_t[ly][lx] = v;
    }
    __syncthreads();

    float sump[CC], inter[CC], cnt[CC];
#pragma unroll
    for (int c = 0; c < CC; c++) { sump[c] = 0.f; inter[c] = 0.f; cnt[c] = 0.f; }
    float ce_s = 0.f, wce_s = 0.f;

    const float* pb = pred + (size_t)b * CC * HWSZ;

#pragma unroll
    for (int r = 0; r < RPT; r++) {
        const int ly = ty + r * BY;         // 0..31 within tile
        const int gy = gy0 + ly;
        const int gx = gx0 + tx;
        const int t  = s_t[ly + 2][tx + 2];

        // ---- 5x5 ellipse morphology: boundary iff max != min over 17 taps ----
        int mx = t;
        unsigned mn = (unsigned)t;
        {   // dy = -2 and +2: center column only
            int v0 = s_t[ly][tx + 2];
            int v1 = s_t[ly + 4][tx + 2];
            mx = max(mx, v0); mn = min(mn, (unsigned)v0);
            mx = max(mx, v1); mn = min(mn, (unsigned)v1);
        }
#pragma unroll
        for (int dy = 1; dy <= 3; dy++) {
#pragma unroll
            for (int dx = 0; dx < 5; dx++) {
                int v = s_t[ly + dy][tx + dx];
                mx = max(mx, v); mn = min(mn, (unsigned)v);
            }
        }
        const bool boundary = (mx != (int)mn);

        // ---- softmax over 8 channels ----
        const size_t base = (size_t)gy * WW + gx;
        float x[CC];
#pragma unroll
        for (int c = 0; c < CC; c++) x[c] = __ldg(pb + base + (size_t)c * HWSZ);

        float m = x[0];
#pragma unroll
        for (int c = 1; c < CC; c++) m = fmaxf(m, x[c]);

        float e[CC], se = 0.f, xt = 0.f;
#pragma unroll
        for (int c = 0; c < CC; c++) {
            e[c] = __expf(x[c] - m);
            se += e[c];
            xt = (c == t) ? x[c] : xt;     // predicated select, no spill
        }
        const float inv = 1.0f / se;
        const float ce  = __logf(se) + m - xt;   // -log_softmax at target channel

#pragma unroll
        for (int c = 0; c < CC; c++) {
            float p = e[c] * inv;
            sump[c] += p;
            bool is = (c == t);
            inter[c] += is ? p : 0.f;
            cnt[c]   += is ? 1.f : 0.f;
        }

        ce_s  += ce;
        wce_s += boundary ? 10.0f * ce : ce;
    }

    // ---- block reduction: warp shuffle, then cross-warp via shared ----
    float q[NQ];
#pragma unroll
    for (int c = 0; c < CC; c++) { q[c] = sump[c]; q[8 + c] = inter[c]; q[16 + c] = cnt[c]; }
    q[24] = ce_s;
    q[25] = wce_s;

    const int lane = tid & 31;
    const int warp = tid >> 5;
#pragma unroll
    for (int k = 0; k < NQ; k++) {
        float v = q[k];
#pragma unroll
        for (int off = 16; off > 0; off >>= 1)
            v += __shfl_down_sync(0xFFFFFFFFu, v, off);
        if (lane == 0) s_red[k][warp] = v;
    }
    __syncthreads();

    if (tid < NQ) {
        float s = 0.f;
#pragma unroll
        for (int w = 0; w < NWARPS; w++) s += s_red[tid][w];
        atomicAdd(&g_acc[b][tid], (double)s);
    }
}

__global__ void finalize_kernel(float* __restrict__ out) {
    // single thread: 64 dice terms + global means
    const double SMOOTH = 1e-06;
    double sum_dice = 0.0, ce = 0.0, wce = 0.0;
    for (int b = 0; b < BB; b++) {
        for (int c = 0; c < CC; c++) {
            double it   = g_acc[b][8 + c];
            double card = g_acc[b][c] + g_acc[b][16 + c];
            sum_dice += (2.0 * it + SMOOTH) / (card + SMOOTH);
        }
        ce  += g_acc[b][24];
        wce += g_acc[b][25];
    }
    const double N = (double)BB * HH * WW;
    double dice = 1.0 - sum_dice / (double)(BB * CC);
    double loss = 1.0 * (ce / N) + 3.0 * dice + 2.0 * (wce / N);
    out[0] = (float)loss;
}

extern "C" void kernel_launch(void* const* d_in, const int* in_sizes, int n_in,
                              void* d_out, int out_size)
{
    const float* pred  = (const float*)d_in[0];
    const int*   target = (const int*)d_in[1];
    float* out = (float*)d_out;

    zero_kernel<<<1, 256>>>();

    dim3 block(BX, BY, 1);
    dim3 grid(WW / TILE, HH / TILE, BB);
    loss_main_kernel<<<grid, block>>>(pred, target);

    finalize_kernel<<<1, 1>>>(out);
}